// round 10
// baseline (speedup 1.0000x reference)
#include <cuda_runtime.h>
#include <cuda_bf16.h>

// binnings: out[b,g,h,w] = sum_n x[b, IDX[g,n], h, w] * groupn[g,n]
//   x: (8, 64, 512, 512) fp32, groupn: (16, 4) fp32, out: (8, 16, 512, 512)
//   IDX[g,n] = (g/4)*16 + n*4 + (g%4)
//
// FINAL. HBM-bound at provably-minimal traffic (640 MiB: IDX partitions
// the 64 input channels exactly — every input element read once, every
// output written once, no cross-g reuse). Pinned at the chip's
// mixed-read/write streaming ceiling: 88.7-89.1% dram__cycles_active,
// 7.03-7.06 TB/s, compute pipes ~5%. Nine rounds of structural variants
// (cache policies x5, MLP x2, CTA size x2, ordering x2, persistence)
// all within ~1%; this config is the reproduced best (96.13us).
//
// Shape: one float4 per thread, 256-thread CTAs, 32768 CTAs with
// pixel-chunks fastest-varying (concentrated ordering won on DRAM row
// locality), default-cached reads (4 independent coalesced LDG.128
// streams), write-through stores (no dirty-L2 carryover between graph
// replays).

static constexpr int B = 8;
static constexpr int C = 64;
static constexpr int G = 16;
static constexpr int HW = 512 * 512;
static constexpr int HW4 = HW / 4;            // 65536 float4s per plane

__global__ __launch_bounds__(256)
void binnings_kernel(const float4* __restrict__ x,
                     const float* __restrict__ groupn,
                     float4* __restrict__ out)
{
    const int g = blockIdx.y;      // 0..15
    const int b = blockIdx.z;      // 0..7
    const int p = blockIdx.x * blockDim.x + threadIdx.x;   // float4 index in plane

    const int ch_base = (g >> 2) * 16 + (g & 3);

    const float w0 = __ldg(&groupn[g * 4 + 0]);
    const float w1 = __ldg(&groupn[g * 4 + 1]);
    const float w2 = __ldg(&groupn[g * 4 + 2]);
    const float w3 = __ldg(&groupn[g * 4 + 3]);

    const long long base = (long long)(b * C + ch_base) * HW4 + p;

    const float4 a0 = __ldg(&x[base + 0LL * 4 * HW4]);
    const float4 a1 = __ldg(&x[base + 1LL * 4 * HW4]);
    const float4 a2 = __ldg(&x[base + 2LL * 4 * HW4]);
    const float4 a3 = __ldg(&x[base + 3LL * 4 * HW4]);

    float4 r;
    r.x = fmaf(a0.x, w0, fmaf(a1.x, w1, fmaf(a2.x, w2, a3.x * w3)));
    r.y = fmaf(a0.y, w0, fmaf(a1.y, w1, fmaf(a2.y, w2, a3.y * w3)));
    r.z = fmaf(a0.z, w0, fmaf(a1.z, w1, fmaf(a2.z, w2, a3.z * w3)));
    r.w = fmaf(a0.w, w0, fmaf(a1.w, w1, fmaf(a2.w, w2, a3.w * w3)));

    __stwt(&out[(long long)(b * G + g) * HW4 + p], r);
}

extern "C" void kernel_launch(void* const* d_in, const int* in_sizes, int n_in,
                              void* d_out, int out_size)
{
    const float4* x      = (const float4*)d_in[0];
    const float*  groupn = (const float*)d_in[1];
    float4*       out    = (float4*)d_out;

    dim3 block(256);
    dim3 grid(HW4 / 256, G, B);   // 256 x 16 x 8 = 32768 blocks
    binnings_kernel<<<grid, block>>>(x, groupn, out);
}

// round 11
// speedup vs baseline: 1.0040x; 1.0040x over previous
#include <cuda_runtime.h>
#include <cuda_bf16.h>

// binnings: out[b,g,h,w] = sum_n x[b, IDX[g,n], h, w] * groupn[g,n]
//   x: (8, 64, 512, 512) fp32, groupn: (16, 4) fp32, out: (8, 16, 512, 512)
//   IDX[g,n] = (g/4)*16 + n*4 + (g%4)
//
// HBM-bound at provably-minimal traffic (640 MiB; IDX partitions the
// 64 channels exactly, zero reuse). Pinned at the mixed-stream ceiling:
// 89-90% dram__cycles_active / 7.0-7.1 TB/s, same-source noise band
// 96.1-96.7us dur_us. R11: the one untested structural point — 512-thread
// CTAs (4 CTAs/SM x 16 warps = full 64-warp occupancy like TPB=256, but
// half the CTA count / preamble work; avoids TPB=1024's occupancy
// quantization loss). Everything else identical to the reproduced best.

static constexpr int B = 8;
static constexpr int C = 64;
static constexpr int G = 16;
static constexpr int HW = 512 * 512;
static constexpr int HW4 = HW / 4;            // 65536 float4s per plane
static constexpr int TPB = 512;

__global__ __launch_bounds__(TPB)
void binnings_kernel(const float4* __restrict__ x,
                     const float* __restrict__ groupn,
                     float4* __restrict__ out)
{
    const int g = blockIdx.y;      // 0..15
    const int b = blockIdx.z;      // 0..7
    const int p = blockIdx.x * TPB + threadIdx.x;   // float4 index in plane

    const int ch_base = (g >> 2) * 16 + (g & 3);

    const float w0 = __ldg(&groupn[g * 4 + 0]);
    const float w1 = __ldg(&groupn[g * 4 + 1]);
    const float w2 = __ldg(&groupn[g * 4 + 2]);
    const float w3 = __ldg(&groupn[g * 4 + 3]);

    const long long base = (long long)(b * C + ch_base) * HW4 + p;

    const float4 a0 = __ldg(&x[base + 0LL * 4 * HW4]);
    const float4 a1 = __ldg(&x[base + 1LL * 4 * HW4]);
    const float4 a2 = __ldg(&x[base + 2LL * 4 * HW4]);
    const float4 a3 = __ldg(&x[base + 3LL * 4 * HW4]);

    float4 r;
    r.x = fmaf(a0.x, w0, fmaf(a1.x, w1, fmaf(a2.x, w2, a3.x * w3)));
    r.y = fmaf(a0.y, w0, fmaf(a1.y, w1, fmaf(a2.y, w2, a3.y * w3)));
    r.z = fmaf(a0.z, w0, fmaf(a1.z, w1, fmaf(a2.z, w2, a3.z * w3)));
    r.w = fmaf(a0.w, w0, fmaf(a1.w, w1, fmaf(a2.w, w2, a3.w * w3)));

    __stwt(&out[(long long)(b * G + g) * HW4 + p], r);
}

extern "C" void kernel_launch(void* const* d_in, const int* in_sizes, int n_in,
                              void* d_out, int out_size)
{
    const float4* x      = (const float4*)d_in[0];
    const float*  groupn = (const float*)d_in[1];
    float4*       out    = (float4*)d_out;

    dim3 block(TPB);
    dim3 grid(HW4 / TPB, G, B);   // 128 x 16 x 8 = 16384 blocks
    binnings_kernel<<<grid, block>>>(x, groupn, out);
}

// round 12
// speedup vs baseline: 1.0050x; 1.0010x over previous
#include <cuda_runtime.h>
#include <cuda_bf16.h>

// binnings: out[b,g,h,w] = sum_n x[b, IDX[g,n], h, w] * groupn[g,n]
//   x: (8, 64, 512, 512) fp32, groupn: (16, 4) fp32, out: (8, 16, 512, 512)
//   IDX[g,n] = (g/4)*16 + n*4 + (g%4)
//
// FINAL (reproduced best, R8 config). HBM-bound at provably-minimal
// traffic: IDX partitions the 64 input channels exactly, so every input
// element is read once and every output written once (640 MiB total,
// zero reuse). Measured at the chip's mixed-read/write streaming
// ceiling across 11 rounds: 88.7-90.1% dram__cycles_active,
// 7.03-7.14 TB/s, compute pipes ~5%, kernel ~92us = 640MiB / 7.1TB/s.
// All structural variants (cache policies x5, MLP x2, CTA size x3,
// ordering x2, persistence) within ~1%; persistent grid-stride and
// spread CTA ordering measurably worse.
//
// Shape: one float4 per thread, 256-thread CTAs, 3D grid with
// pixel-chunks fastest (concentrated ordering -> DRAM row locality),
// default-cached reads (4 independent coalesced LDG.128 streams),
// write-through stores (no dirty-L2 carryover between graph replays).

static constexpr int B = 8;
static constexpr int C = 64;
static constexpr int G = 16;
static constexpr int HW = 512 * 512;
static constexpr int HW4 = HW / 4;            // 65536 float4s per plane

__global__ __launch_bounds__(256)
void binnings_kernel(const float4* __restrict__ x,
                     const float* __restrict__ groupn,
                     float4* __restrict__ out)
{
    const int g = blockIdx.y;      // 0..15
    const int b = blockIdx.z;      // 0..7
    const int p = blockIdx.x * blockDim.x + threadIdx.x;   // float4 index in plane

    const int ch_base = (g >> 2) * 16 + (g & 3);

    const float w0 = __ldg(&groupn[g * 4 + 0]);
    const float w1 = __ldg(&groupn[g * 4 + 1]);
    const float w2 = __ldg(&groupn[g * 4 + 2]);
    const float w3 = __ldg(&groupn[g * 4 + 3]);

    const long long base = (long long)(b * C + ch_base) * HW4 + p;

    const float4 a0 = __ldg(&x[base + 0LL * 4 * HW4]);
    const float4 a1 = __ldg(&x[base + 1LL * 4 * HW4]);
    const float4 a2 = __ldg(&x[base + 2LL * 4 * HW4]);
    const float4 a3 = __ldg(&x[base + 3LL * 4 * HW4]);

    float4 r;
    r.x = fmaf(a0.x, w0, fmaf(a1.x, w1, fmaf(a2.x, w2, a3.x * w3)));
    r.y = fmaf(a0.y, w0, fmaf(a1.y, w1, fmaf(a2.y, w2, a3.y * w3)));
    r.z = fmaf(a0.z, w0, fmaf(a1.z, w1, fmaf(a2.z, w2, a3.z * w3)));
    r.w = fmaf(a0.w, w0, fmaf(a1.w, w1, fmaf(a2.w, w2, a3.w * w3)));

    __stwt(&out[(long long)(b * G + g) * HW4 + p], r);
}

extern "C" void kernel_launch(void* const* d_in, const int* in_sizes, int n_in,
                              void* d_out, int out_size)
{
    const float4* x      = (const float4*)d_in[0];
    const float*  groupn = (const float*)d_in[1];
    float4*       out    = (float4*)d_out;

    dim3 block(256);
    dim3 grid(HW4 / 256, G, B);   // 256 x 16 x 8 = 32768 blocks
    binnings_kernel<<<grid, block>>>(x, groupn, out);
}